// round 14
// baseline (speedup 1.0000x reference)
#include <cuda_runtime.h>

#define NPIX (512*512)
#define D1B 6
#define D1S 3
#define MAXMB (D1B*NPIX+1)
#define MAXMS (D1S*NPIX+1)
#define ALPHA_B (32.0f/33.0f)
#define ALPHA_S 0.8f
#define BI_COMPAT 10.0f
#define SP_COMPAT 3.0f
#define TPB 256

// float4 tables for Q filtering (3-buffer ping-pong per lattice).
__device__ float4 g_tb[3][MAXMB];
__device__ float4 g_ts[3][MAXMS];
// fp32 scalar tables for the ones-filter (2-buffer ping-pong), processed alongside round 0.
__device__ float  g_sb[2][MAXMB];
__device__ float  g_ss[2][MAXMS];
// Composed 2-pass stencil indices (bilateral: stored in RENUMBERED space).
__device__ int    g_cb[3][(size_t)(MAXMB - 1) * 8];
__device__ int    g_cs9[(size_t)(MAXMS - 1) * 8];
__device__ float  g_inb[NPIX];
__device__ float  g_ins[NPIX];
// --- first-touch renumbering scratch (bilateral lattice only) ---
__device__ int    g_key[MAXMB];        // old row id -> min touching pixel
__device__ int    g_cnt[NPIX];         // bucket counts, then scatter cursors
__device__ int    g_basep[NPIX];       // bucket bases (exclusive scan)
__device__ int    g_bsum[256];
__device__ int    g_newid[MAXMB];      // old id -> new id (1-based); [0]=0
__device__ int    g_osb2[(size_t)NPIX * D1B];  // remapped bilateral os

__device__ __forceinline__ void red4(float4* p, float x, float y, float z, float w) {
    asm volatile("red.global.add.v4.f32 [%0], {%1,%2,%3,%4};"
                 :: "l"(p), "f"(x), "f"(y), "f"(z), "f"(w) : "memory");
}
__device__ __forceinline__ void red1(float* p, float v) {
    asm volatile("red.global.add.f32 [%0], %1;" :: "l"(p), "f"(v) : "memory");
}

__device__ __forceinline__ float4 softmax_neg(float4 u, float4 msg) {
    float zx = msg.x - u.x, zy = msg.y - u.y, zz = msg.z - u.z, zw = msg.w - u.w;
    float m = fmaxf(fmaxf(zx, zy), fmaxf(zz, zw));
    float ex = __expf(zx - m), ey = __expf(zy - m), ez = __expf(zz - m), ew = __expf(zw - m);
    float inv = 1.0f / (ex + ey + ez + ew);
    return make_float4(ex * inv, ey * inv, ez * inv, ew * inv);
}

__device__ __forceinline__ float4 gather9(const int4 i0, const int4 i1,
                                          const float4* __restrict__ s, int center) {
    float4 c  = s[center];
    float4 a0 = s[i0.x], a1 = s[i0.y];
    float4 n1 = s[i0.z], n1a = s[i0.w], n1b = s[i1.x];
    float4 n2 = s[i1.y], n2a = s[i1.z], n2b = s[i1.w];
    float4 r;
    r.x = c.x + 0.5f * (a0.x + a1.x + n1.x + n2.x) + 0.25f * (n1a.x + n1b.x + n2a.x + n2b.x);
    r.y = c.y + 0.5f * (a0.y + a1.y + n1.y + n2.y) + 0.25f * (n1a.y + n1b.y + n2a.y + n2b.y);
    r.z = c.z + 0.5f * (a0.z + a1.z + n1.z + n2.z) + 0.25f * (n1a.z + n1b.z + n2a.z + n2b.z);
    r.w = c.w + 0.5f * (a0.w + a1.w + n1.w + n2.w) + 0.25f * (n1a.w + n1b.w + n2a.w + n2b.w);
    return r;
}

__device__ __forceinline__ float gather9s(const int4 i0, const int4 i1,
                                          const float* __restrict__ s, int center) {
    return s[center]
         + 0.5f  * (s[i0.x] + s[i0.y] + s[i0.z] + s[i1.y])
         + 0.25f * (s[i0.w] + s[i1.x] + s[i1.z] + s[i1.w]);
}

// ---------------- Renumbering pipeline (one-time) ----------------

__global__ void __launch_bounds__(TPB) r_init(int Mb) {
    int t = blockIdx.x * blockDim.x + threadIdx.x;
    if (t < NPIX) g_cnt[t] = 0;
    if (t <= Mb) g_key[t] = 0x7fffffff;
}

__global__ void __launch_bounds__(TPB) r_key(const int* __restrict__ osb) {
    int n = blockIdx.x * blockDim.x + threadIdx.x;
    if (n >= NPIX) return;
#pragma unroll
    for (int r = 0; r < D1B; r++)
        atomicMin(&g_key[osb[n * D1B + r]], n);
}

__global__ void __launch_bounds__(TPB) r_hist(int Mb) {
    int t = blockIdx.x * blockDim.x + threadIdx.x;
    int m = t + 1;
    if (m <= Mb) atomicAdd(&g_cnt[g_key[m]], 1);
}

// scanA: 256 blocks x 256 threads x 4 elems -> per-block exclusive scan + block sums.
__global__ void __launch_bounds__(256) r_scanA() {
    __shared__ int sh[256];
    int tid = threadIdx.x;
    int i0 = (blockIdx.x * 256 + tid) * 4;
    int4 v = *(const int4*)&g_cnt[i0];
    int s = v.x + v.y + v.z + v.w;
    sh[tid] = s;
    __syncthreads();
    for (int off = 1; off < 256; off <<= 1) {
        int a = (tid >= off) ? sh[tid - off] : 0;
        __syncthreads();
        sh[tid] += a;
        __syncthreads();
    }
    int excl = sh[tid] - s;
    g_basep[i0]     = excl;
    g_basep[i0 + 1] = excl + v.x;
    g_basep[i0 + 2] = excl + v.x + v.y;
    g_basep[i0 + 3] = excl + v.x + v.y + v.z;
    if (tid == 255) g_bsum[blockIdx.x] = sh[255];
}

__global__ void __launch_bounds__(256) r_scanB() {
    __shared__ int sh[256];
    int tid = threadIdx.x;
    int s = g_bsum[tid];
    sh[tid] = s;
    __syncthreads();
    for (int off = 1; off < 256; off <<= 1) {
        int a = (tid >= off) ? sh[tid - off] : 0;
        __syncthreads();
        sh[tid] += a;
        __syncthreads();
    }
    g_bsum[tid] = sh[tid] - s;   // exclusive
}

__global__ void __launch_bounds__(TPB) r_scanC() {
    int i = blockIdx.x * blockDim.x + threadIdx.x;
    if (i >= NPIX) return;
    g_basep[i] += g_bsum[i >> 10];
    g_cnt[i] = 0;                // reuse as scatter cursor
}

__global__ void __launch_bounds__(TPB) r_scatter(int Mb) {
    int t = blockIdx.x * blockDim.x + threadIdx.x;
    if (t == 0) g_newid[0] = 0;
    int m = t + 1;
    if (m <= Mb) {
        int k = g_key[m];
        g_newid[m] = 1 + g_basep[k] + atomicAdd(&g_cnt[k], 1);
    }
}

__global__ void __launch_bounds__(TPB) r_remap(const int* __restrict__ osb) {
    int n = blockIdx.x * blockDim.x + threadIdx.x;
    if (n >= NPIX) return;
#pragma unroll
    for (int r = 0; r < D1B; r++)
        g_osb2[n * D1B + r] = g_newid[osb[n * D1B + r]];
}

// Build composed 2-pass stencils (bilateral in NEW numbering); zero splat buffers.
__global__ void __launch_bounds__(TPB) compose_zero(const int2* __restrict__ bnb, int Mb,
                                                    const int2* __restrict__ bns, int Ms) {
    int t = blockIdx.x * blockDim.x + threadIdx.x;
    if (t <= Mb) { g_sb[0][t] = 0.f; g_tb[0][t] = make_float4(0.f, 0.f, 0.f, 0.f); }
    if (t <= Ms) { g_ss[0][t] = 0.f; g_ts[0][t] = make_float4(0.f, 0.f, 0.f, 0.f); }
    if (t < Mb) {
        int p = g_newid[t + 1];   // new row id for old row t+1
#pragma unroll
        for (int pp = 0; pp < 3; pp++) {
            const int2* r1 = bnb + (size_t)(2 * pp) * Mb;
            const int2* r2 = bnb + (size_t)(2 * pp + 1) * Mb;
            int2 ab = r1[t];
            int2 nn = r2[t];
            int o3 = 0, o4 = 0, o6 = 0, o7 = 0;
            if (nn.x > 0) { int2 c = r1[nn.x - 1]; o3 = c.x; o4 = c.y; }
            if (nn.y > 0) { int2 c = r1[nn.y - 1]; o6 = c.x; o7 = c.y; }
            int4* dst = (int4*)&g_cb[pp][(size_t)(p - 1) * 8];
            dst[0] = make_int4(g_newid[ab.x], g_newid[ab.y], g_newid[nn.x], g_newid[o3]);
            dst[1] = make_int4(g_newid[o4], g_newid[nn.y], g_newid[o6], g_newid[o7]);
        }
    } else {
        int m = t - Mb;
        if (m < Ms) {
            const int2* r1 = bns;
            const int2* r2 = bns + (size_t)Ms;
            int2 ab = r1[m];
            int2 nn = r2[m];
            int o3 = 0, o4 = 0, o6 = 0, o7 = 0;
            if (nn.x > 0) { int2 c = r1[nn.x - 1]; o3 = c.x; o4 = c.y; }
            if (nn.y > 0) { int2 c = r1[nn.y - 1]; o6 = c.x; o7 = c.y; }
            int4* dst = (int4*)&g_cs9[(size_t)m * 8];
            dst[0] = make_int4(ab.x, ab.y, nn.x, o3);
            dst[1] = make_int4(o4, nn.y, o6, o7);
        }
    }
}

// ---------------- Main pipeline ----------------

// P1: Q0 = softmax(-u); splat ones (scalar) AND Q0 (float4). Bilateral uses remapped os.
__global__ void __launch_bounds__(TPB) splat0(
        const float4* __restrict__ unary,
        const float* __restrict__ wsb,
        const int* __restrict__ oss, const float* __restrict__ wss) {
    int n = blockIdx.x * blockDim.x + threadIdx.x;
    if (n >= NPIX) return;
    float4 q = softmax_neg(unary[n], make_float4(0.f, 0.f, 0.f, 0.f));
#pragma unroll
    for (int r = 0; r < D1B; r++) {
        int o = g_osb2[n * D1B + r];
        float w = wsb[n * D1B + r];
        red1(&g_sb[0][o], w);
        red4(&g_tb[0][o], q.x * w, q.y * w, q.z * w, q.w * w);
    }
#pragma unroll
    for (int r = 0; r < D1S; r++) {
        int o = oss[n * D1S + r];
        float w = wss[n * D1S + r];
        red1(&g_ss[0][o], w);
        red4(&g_ts[0][o], q.x * w, q.y * w, q.z * w, q.w * w);
    }
}

template<int FUSE_ONES>
__global__ void __launch_bounds__(TPB) k1t(int Mb, int Ms) {
    int t = blockIdx.x * blockDim.x + threadIdx.x;
    if (t < Mb) {
        const int4* ip = (const int4*)&g_cb[0][(size_t)t * 8];
        int4 i0 = ip[0], i1 = ip[1];
        g_tb[1][t + 1] = gather9(i0, i1, g_tb[0], t + 1);
        if (FUSE_ONES) g_sb[1][t + 1] = gather9s(i0, i1, g_sb[0], t + 1);
        if (t == 0) {
            g_tb[1][0] = make_float4(0.f, 0.f, 0.f, 0.f);
            if (FUSE_ONES) g_sb[1][0] = 0.f;
        }
    } else {
        int m = t - Mb;
        if (m < Ms) {
            const int4* ip = (const int4*)&g_cs9[(size_t)m * 8];
            int4 i0 = ip[0], i1 = ip[1];
            g_ts[1][m + 1] = gather9(i0, i1, g_ts[0], m + 1);
            if (FUSE_ONES) g_ss[1][m + 1] = gather9s(i0, i1, g_ss[0], m + 1);
            if (m == 0) {
                g_ts[1][0] = make_float4(0.f, 0.f, 0.f, 0.f);
                if (FUSE_ONES) g_ss[1][0] = 0.f;
            }
        }
    }
}

template<int FUSE_ONES>
__global__ void __launch_bounds__(TPB) k2t(int Mb, const int2* __restrict__ bns, int Ms) {
    int t = blockIdx.x * blockDim.x + threadIdx.x;
    if (t < Mb) {
        const int4* ip = (const int4*)&g_cb[1][(size_t)t * 8];
        int4 i0 = ip[0], i1 = ip[1];
        g_tb[2][t + 1] = gather9(i0, i1, g_tb[1], t + 1);
        if (FUSE_ONES) g_sb[0][t + 1] = gather9s(i0, i1, g_sb[1], t + 1);
        g_tb[0][t + 1] = make_float4(0.f, 0.f, 0.f, 0.f);
        if (t == 0) {
            g_tb[2][0] = make_float4(0.f, 0.f, 0.f, 0.f);
            g_tb[0][0] = make_float4(0.f, 0.f, 0.f, 0.f);
            if (FUSE_ONES) g_sb[0][0] = 0.f;
        }
    } else {
        int m = t - Mb;
        if (m < Ms) {
            int2 nb = bns[(size_t)2 * Ms + m];
            const float4* __restrict__ s = g_ts[1];
            float4 c = s[m + 1], a = s[nb.x], b = s[nb.y];
            g_ts[2][m + 1] = make_float4(c.x + 0.5f * (a.x + b.x), c.y + 0.5f * (a.y + b.y),
                                         c.z + 0.5f * (a.z + b.z), c.w + 0.5f * (a.w + b.w));
            if (FUSE_ONES)
                g_ss[0][m + 1] = g_ss[1][m + 1] + 0.5f * (g_ss[1][nb.x] + g_ss[1][nb.y]);
            g_ts[0][m + 1] = make_float4(0.f, 0.f, 0.f, 0.f);
            if (m == 0) {
                g_ts[2][0] = make_float4(0.f, 0.f, 0.f, 0.f);
                g_ts[0][0] = make_float4(0.f, 0.f, 0.f, 0.f);
                if (FUSE_ONES) g_ss[0][0] = 0.f;
            }
        }
    }
}

template<int FUSE_ONES>
__global__ void __launch_bounds__(TPB) k3t(int Mb) {
    int t = blockIdx.x * blockDim.x + threadIdx.x;
    if (t >= Mb) return;
    const int4* ip = (const int4*)&g_cb[2][(size_t)t * 8];
    int4 i0 = ip[0], i1 = ip[1];
    g_tb[1][t + 1] = gather9(i0, i1, g_tb[2], t + 1);
    if (FUSE_ONES) g_sb[1][t + 1] = gather9s(i0, i1, g_sb[0], t + 1);
    if (t == 0) {
        g_tb[1][0] = make_float4(0.f, 0.f, 0.f, 0.f);
        if (FUSE_ONES) g_sb[1][0] = 0.f;
    }
}

// Slice + mean-field update + splat of next Q (or final write).
template<int NORM>
__global__ void __launch_bounds__(TPB) slice_t(
        const float4* __restrict__ unary,
        const float* __restrict__ wsb,
        const int* __restrict__ oss, const float* __restrict__ wss,
        float4* __restrict__ outp, int write_out) {
    int n = blockIdx.x * blockDim.x + threadIdx.x;
    if (n >= NPIX) return;
    float4 fb = make_float4(0.f, 0.f, 0.f, 0.f);
    float  nb = 0.f;
    int   ob[D1B];
    float wb[D1B];
#pragma unroll
    for (int r = 0; r < D1B; r++) {
        ob[r] = g_osb2[n * D1B + r];
        wb[r] = wsb[n * D1B + r];
        float4 v = g_tb[1][ob[r]];
        fb.x += v.x * wb[r]; fb.y += v.y * wb[r]; fb.z += v.z * wb[r]; fb.w += v.w * wb[r];
        if (NORM) nb += g_sb[1][ob[r]] * wb[r];
    }
    float4 fs = make_float4(0.f, 0.f, 0.f, 0.f);
    float  ns = 0.f;
    int   osr[D1S];
    float wsr[D1S];
#pragma unroll
    for (int r = 0; r < D1S; r++) {
        osr[r] = oss[n * D1S + r];
        wsr[r] = wss[n * D1S + r];
        float4 v = g_ts[2][osr[r]];
        fs.x += v.x * wsr[r]; fs.y += v.y * wsr[r]; fs.z += v.z * wsr[r]; fs.w += v.w * wsr[r];
        if (NORM) ns += g_ss[0][osr[r]] * wsr[r];
    }
    float inb, ins;
    if (NORM) {
        inb = 1.0f / (ALPHA_B * nb + 1e-20f);
        ins = 1.0f / (ALPHA_S * ns + 1e-20f);
        g_inb[n] = inb;
        g_ins[n] = ins;
    } else {
        inb = g_inb[n];
        ins = g_ins[n];
    }
    float cb = BI_COMPAT * ALPHA_B * inb;
    float cs = SP_COMPAT * ALPHA_S * ins;
    float4 msg = make_float4(fb.x * cb + fs.x * cs, fb.y * cb + fs.y * cs,
                             fb.z * cb + fs.z * cs, fb.w * cb + fs.w * cs);
    float4 q = softmax_neg(unary[n], msg);
    if (write_out) {
        outp[n] = q;
    } else {
#pragma unroll
        for (int r = 0; r < D1B; r++)
            red4(&g_tb[0][ob[r]], q.x * wb[r], q.y * wb[r], q.z * wb[r], q.w * wb[r]);
#pragma unroll
        for (int r = 0; r < D1S; r++)
            red4(&g_ts[0][osr[r]], q.x * wsr[r], q.y * wsr[r], q.z * wsr[r], q.w * wsr[r]);
    }
}

extern "C" void kernel_launch(void* const* d_in, const int* in_sizes, int n_in,
                              void* d_out, int out_size) {
    const float4* unary = (const float4*)d_in[0];
    const float*  wsb   = (const float*)d_in[1];
    const int*    osb   = (const int*)d_in[2];
    const int2*   bnb   = (const int2*)d_in[3];
    const float*  wss   = (const float*)d_in[5];
    const int*    oss   = (const int*)d_in[6];
    const int2*   bns   = (const int2*)d_in[7];

    int Mb = in_sizes[3] / (D1B * 2);   // blur_neighbors_bilateral: [6, Mb, 2]
    int Ms = in_sizes[7] / (D1S * 2);   // blur_neighbors_spatial:   [3, Ms, 2]

    const int nblk = (NPIX + TPB - 1) / TPB;
    const int cblk = (Mb + Ms + TPB - 1) / TPB;
    const int bblk = (Mb + TPB - 1) / TPB;
    int imax = (NPIX > Mb + 1) ? NPIX : Mb + 1;
    const int iblk = (imax + TPB - 1) / TPB;

    // ---- First-touch renumbering of the bilateral lattice ----
    r_init<<<iblk, TPB>>>(Mb);
    r_key<<<nblk, TPB>>>(osb);
    r_hist<<<bblk, TPB>>>(Mb);
    r_scanA<<<256, 256>>>();
    r_scanB<<<1, 256>>>();
    r_scanC<<<nblk, TPB>>>();
    r_scatter<<<bblk, TPB>>>(Mb);
    r_remap<<<nblk, TPB>>>(osb);

    // ---- Init: stencils (new numbering) + zero, then fused ones+Q0 splat ----
    compose_zero<<<cblk, TPB>>>(bnb, Mb, bns, Ms);
    splat0<<<nblk, TPB>>>(unary, wsb, oss, wss);

    // ---- Round 0: blur ones alongside Q, compute norms inline in slice ----
    k1t<1><<<cblk, TPB>>>(Mb, Ms);
    k2t<1><<<cblk, TPB>>>(Mb, bns, Ms);
    k3t<1><<<bblk, TPB>>>(Mb);
    slice_t<1><<<nblk, TPB>>>(unary, wsb, oss, wss, (float4*)d_out, 0);

    // ---- Rounds 1-9 ----
    for (int it = 1; it < 10; it++) {
        k1t<0><<<cblk, TPB>>>(Mb, Ms);
        k2t<0><<<cblk, TPB>>>(Mb, bns, Ms);
        k3t<0><<<bblk, TPB>>>(Mb);
        slice_t<0><<<nblk, TPB>>>(unary, wsb, oss, wss,
                                  (float4*)d_out, it == 9 ? 1 : 0);
    }
}

// round 16
// speedup vs baseline: 1.4057x; 1.4057x over previous
#include <cuda_runtime.h>

#define NPIX (512*512)
#define D1B 6
#define D1S 3
#define MAXMB (D1B*NPIX+1)
#define MAXMS (D1S*NPIX+1)
#define ALPHA_B (32.0f/33.0f)
#define ALPHA_S 0.8f
#define BI_COMPAT 10.0f
#define SP_COMPAT 3.0f
#define TPB 256

// float4 tables for Q filtering (3-buffer ping-pong per lattice).
__device__ float4 g_tb[3][MAXMB];
__device__ float4 g_ts[3][MAXMS];
// fp32 scalar tables for the ones-filter (2-buffer ping-pong), processed alongside round 0.
__device__ float  g_sb[2][MAXMB];
__device__ float  g_ss[2][MAXMS];
// Composed 2-pass stencil indices: bilateral pairs (0,1),(2,3),(4,5); spatial pair (0,1).
__device__ int    g_cb[3][(size_t)(MAXMB - 1) * 8];
__device__ int    g_cs9[(size_t)(MAXMS - 1) * 8];
__device__ float  g_inb[NPIX];
__device__ float  g_ins[NPIX];

__device__ __forceinline__ void red4(float4* p, float x, float y, float z, float w) {
    asm volatile("red.global.add.v4.f32 [%0], {%1,%2,%3,%4};"
                 :: "l"(p), "f"(x), "f"(y), "f"(z), "f"(w) : "memory");
}
__device__ __forceinline__ void red1(float* p, float v) {
    asm volatile("red.global.add.f32 [%0], %1;" :: "l"(p), "f"(v) : "memory");
}

__device__ __forceinline__ float4 softmax_neg(float4 u, float4 msg) {
    float zx = msg.x - u.x, zy = msg.y - u.y, zz = msg.z - u.z, zw = msg.w - u.w;
    float m = fmaxf(fmaxf(zx, zy), fmaxf(zz, zw));
    float ex = __expf(zx - m), ey = __expf(zy - m), ez = __expf(zz - m), ew = __expf(zw - m);
    float inv = 1.0f / (ex + ey + ez + ew);
    return make_float4(ex * inv, ey * inv, ez * inv, ew * inv);
}

__device__ __forceinline__ float4 gather9(const int4 i0, const int4 i1,
                                          const float4* __restrict__ s, int center) {
    float4 c  = s[center];
    float4 a0 = s[i0.x], a1 = s[i0.y];
    float4 n1 = s[i0.z], n1a = s[i0.w], n1b = s[i1.x];
    float4 n2 = s[i1.y], n2a = s[i1.z], n2b = s[i1.w];
    float4 r;
    r.x = c.x + 0.5f * (a0.x + a1.x + n1.x + n2.x) + 0.25f * (n1a.x + n1b.x + n2a.x + n2b.x);
    r.y = c.y + 0.5f * (a0.y + a1.y + n1.y + n2.y) + 0.25f * (n1a.y + n1b.y + n2a.y + n2b.y);
    r.z = c.z + 0.5f * (a0.z + a1.z + n1.z + n2.z) + 0.25f * (n1a.z + n1b.z + n2a.z + n2b.z);
    r.w = c.w + 0.5f * (a0.w + a1.w + n1.w + n2.w) + 0.25f * (n1a.w + n1b.w + n2a.w + n2b.w);
    return r;
}

__device__ __forceinline__ float gather9s(const int4 i0, const int4 i1,
                                          const float* __restrict__ s, int center) {
    return s[center]
         + 0.5f  * (s[i0.x] + s[i0.y] + s[i0.z] + s[i1.y])
         + 0.25f * (s[i0.w] + s[i1.x] + s[i1.z] + s[i1.w]);
}

// P0: build composed 2-pass stencils; zero all splat buffers (scalar + float4).
__global__ void __launch_bounds__(TPB) compose_zero(const int2* __restrict__ bnb, int Mb,
                                                    const int2* __restrict__ bns, int Ms) {
    int t = blockIdx.x * blockDim.x + threadIdx.x;
    if (t <= Mb) { g_sb[0][t] = 0.f; g_tb[0][t] = make_float4(0.f, 0.f, 0.f, 0.f); }
    if (t <= Ms) { g_ss[0][t] = 0.f; g_ts[0][t] = make_float4(0.f, 0.f, 0.f, 0.f); }
    if (t < Mb) {
#pragma unroll
        for (int p = 0; p < 3; p++) {
            const int2* r1 = bnb + (size_t)(2 * p) * Mb;
            const int2* r2 = bnb + (size_t)(2 * p + 1) * Mb;
            int2 ab = r1[t];
            int2 nn = r2[t];
            int o3 = 0, o4 = 0, o6 = 0, o7 = 0;
            if (nn.x > 0) { int2 c = r1[nn.x - 1]; o3 = c.x; o4 = c.y; }
            if (nn.y > 0) { int2 c = r1[nn.y - 1]; o6 = c.x; o7 = c.y; }
            int4* dst = (int4*)&g_cb[p][(size_t)t * 8];
            dst[0] = make_int4(ab.x, ab.y, nn.x, o3);
            dst[1] = make_int4(o4, nn.y, o6, o7);
        }
    } else {
        int m = t - Mb;
        if (m < Ms) {
            const int2* r1 = bns;
            const int2* r2 = bns + (size_t)Ms;
            int2 ab = r1[m];
            int2 nn = r2[m];
            int o3 = 0, o4 = 0, o6 = 0, o7 = 0;
            if (nn.x > 0) { int2 c = r1[nn.x - 1]; o3 = c.x; o4 = c.y; }
            if (nn.y > 0) { int2 c = r1[nn.y - 1]; o6 = c.x; o7 = c.y; }
            int4* dst = (int4*)&g_cs9[(size_t)m * 8];
            dst[0] = make_int4(ab.x, ab.y, nn.x, o3);
            dst[1] = make_int4(o4, nn.y, o6, o7);
        }
    }
}

// P1: Q0 = softmax(-u); splat ones (scalar) AND Q0 (float4), one idx read.
__global__ void __launch_bounds__(TPB) splat0(
        const float4* __restrict__ unary,
        const int* __restrict__ osb, const float* __restrict__ wsb,
        const int* __restrict__ oss, const float* __restrict__ wss) {
    int n = blockIdx.x * blockDim.x + threadIdx.x;
    if (n >= NPIX) return;
    float4 q = softmax_neg(unary[n], make_float4(0.f, 0.f, 0.f, 0.f));
#pragma unroll
    for (int r = 0; r < D1B; r++) {
        int o = osb[n * D1B + r];
        float w = wsb[n * D1B + r];
        red1(&g_sb[0][o], w);
        red4(&g_tb[0][o], q.x * w, q.y * w, q.z * w, q.w * w);
    }
#pragma unroll
    for (int r = 0; r < D1S; r++) {
        int o = oss[n * D1S + r];
        float w = wss[n * D1S + r];
        red1(&g_ss[0][o], w);
        red4(&g_ts[0][o], q.x * w, q.y * w, q.z * w, q.w * w);
    }
}

// ---------------- Blur kernels. FUSE_ONES=1 variants also blur the scalar
// ones-tables, reusing the already-loaded stencil indices (round 0 only). ----

template<int FUSE_ONES>
__global__ void __launch_bounds__(TPB) k1t(int Mb, int Ms) {
    int t = blockIdx.x * blockDim.x + threadIdx.x;
    if (t < Mb) {
        const int4* ip = (const int4*)&g_cb[0][(size_t)t * 8];
        int4 i0 = ip[0], i1 = ip[1];
        g_tb[1][t + 1] = gather9(i0, i1, g_tb[0], t + 1);
        if (FUSE_ONES) g_sb[1][t + 1] = gather9s(i0, i1, g_sb[0], t + 1);
        if (t == 0) {
            g_tb[1][0] = make_float4(0.f, 0.f, 0.f, 0.f);
            if (FUSE_ONES) g_sb[1][0] = 0.f;
        }
    } else {
        int m = t - Mb;
        if (m < Ms) {
            const int4* ip = (const int4*)&g_cs9[(size_t)m * 8];
            int4 i0 = ip[0], i1 = ip[1];
            g_ts[1][m + 1] = gather9(i0, i1, g_ts[0], m + 1);
            if (FUSE_ONES) g_ss[1][m + 1] = gather9s(i0, i1, g_ss[0], m + 1);
            if (m == 0) {
                g_ts[1][0] = make_float4(0.f, 0.f, 0.f, 0.f);
                if (FUSE_ONES) g_ss[1][0] = 0.f;
            }
        }
    }
}

template<int FUSE_ONES>
__global__ void __launch_bounds__(TPB) k2t(int Mb, const int2* __restrict__ bns, int Ms) {
    int t = blockIdx.x * blockDim.x + threadIdx.x;
    if (t < Mb) {
        const int4* ip = (const int4*)&g_cb[1][(size_t)t * 8];
        int4 i0 = ip[0], i1 = ip[1];
        g_tb[2][t + 1] = gather9(i0, i1, g_tb[1], t + 1);
        if (FUSE_ONES) g_sb[0][t + 1] = gather9s(i0, i1, g_sb[1], t + 1);
        g_tb[0][t + 1] = make_float4(0.f, 0.f, 0.f, 0.f);
        if (t == 0) {
            g_tb[2][0] = make_float4(0.f, 0.f, 0.f, 0.f);
            g_tb[0][0] = make_float4(0.f, 0.f, 0.f, 0.f);
            if (FUSE_ONES) g_sb[0][0] = 0.f;
        }
    } else {
        int m = t - Mb;
        if (m < Ms) {
            int2 nb = bns[(size_t)2 * Ms + m];
            const float4* __restrict__ s = g_ts[1];
            float4 c = s[m + 1], a = s[nb.x], b = s[nb.y];
            g_ts[2][m + 1] = make_float4(c.x + 0.5f * (a.x + b.x), c.y + 0.5f * (a.y + b.y),
                                         c.z + 0.5f * (a.z + b.z), c.w + 0.5f * (a.w + b.w));
            if (FUSE_ONES)
                g_ss[0][m + 1] = g_ss[1][m + 1] + 0.5f * (g_ss[1][nb.x] + g_ss[1][nb.y]);
            g_ts[0][m + 1] = make_float4(0.f, 0.f, 0.f, 0.f);
            if (m == 0) {
                g_ts[2][0] = make_float4(0.f, 0.f, 0.f, 0.f);
                g_ts[0][0] = make_float4(0.f, 0.f, 0.f, 0.f);
                if (FUSE_ONES) g_ss[0][0] = 0.f;
            }
        }
    }
}

template<int FUSE_ONES>
__global__ void __launch_bounds__(TPB) k3t(int Mb) {
    int t = blockIdx.x * blockDim.x + threadIdx.x;
    if (t >= Mb) return;
    const int4* ip = (const int4*)&g_cb[2][(size_t)t * 8];
    int4 i0 = ip[0], i1 = ip[1];
    g_tb[1][t + 1] = gather9(i0, i1, g_tb[2], t + 1);
    if (FUSE_ONES) g_sb[1][t + 1] = gather9s(i0, i1, g_sb[0], t + 1);
    if (t == 0) {
        g_tb[1][0] = make_float4(0.f, 0.f, 0.f, 0.f);
        if (FUSE_ONES) g_sb[1][0] = 0.f;
    }
}

// Slice + mean-field update + splat of next Q (or final write). Round 0
// (NORM=1) additionally computes the norms inline from the blurred ones-tables.
template<int NORM>
__global__ void __launch_bounds__(TPB) slice_t(
        const float4* __restrict__ unary,
        const int* __restrict__ osb, const float* __restrict__ wsb,
        const int* __restrict__ oss, const float* __restrict__ wss,
        float4* __restrict__ outp, int write_out) {
    int n = blockIdx.x * blockDim.x + threadIdx.x;
    if (n >= NPIX) return;
    float4 fb = make_float4(0.f, 0.f, 0.f, 0.f);
    float  nb = 0.f;
    int   ob[D1B];
    float wb[D1B];
#pragma unroll
    for (int r = 0; r < D1B; r++) {
        ob[r] = osb[n * D1B + r];
        wb[r] = wsb[n * D1B + r];
        float4 v = g_tb[1][ob[r]];
        fb.x += v.x * wb[r]; fb.y += v.y * wb[r]; fb.z += v.z * wb[r]; fb.w += v.w * wb[r];
        if (NORM) nb += g_sb[1][ob[r]] * wb[r];
    }
    float4 fs = make_float4(0.f, 0.f, 0.f, 0.f);
    float  ns = 0.f;
    int   osr[D1S];
    float wsr[D1S];
#pragma unroll
    for (int r = 0; r < D1S; r++) {
        osr[r] = oss[n * D1S + r];
        wsr[r] = wss[n * D1S + r];
        float4 v = g_ts[2][osr[r]];
        fs.x += v.x * wsr[r]; fs.y += v.y * wsr[r]; fs.z += v.z * wsr[r]; fs.w += v.w * wsr[r];
        if (NORM) ns += g_ss[0][osr[r]] * wsr[r];
    }
    float inb, ins;
    if (NORM) {
        inb = 1.0f / (ALPHA_B * nb + 1e-20f);
        ins = 1.0f / (ALPHA_S * ns + 1e-20f);
        g_inb[n] = inb;
        g_ins[n] = ins;
    } else {
        inb = g_inb[n];
        ins = g_ins[n];
    }
    float cb = BI_COMPAT * ALPHA_B * inb;
    float cs = SP_COMPAT * ALPHA_S * ins;
    float4 msg = make_float4(fb.x * cb + fs.x * cs, fb.y * cb + fs.y * cs,
                             fb.z * cb + fs.z * cs, fb.w * cb + fs.w * cs);
    float4 q = softmax_neg(unary[n], msg);
    if (write_out) {
        outp[n] = q;
    } else {
#pragma unroll
        for (int r = 0; r < D1B; r++)
            red4(&g_tb[0][ob[r]], q.x * wb[r], q.y * wb[r], q.z * wb[r], q.w * wb[r]);
#pragma unroll
        for (int r = 0; r < D1S; r++)
            red4(&g_ts[0][osr[r]], q.x * wsr[r], q.y * wsr[r], q.z * wsr[r], q.w * wsr[r]);
    }
}

extern "C" void kernel_launch(void* const* d_in, const int* in_sizes, int n_in,
                              void* d_out, int out_size) {
    const float4* unary = (const float4*)d_in[0];
    const float*  wsb   = (const float*)d_in[1];
    const int*    osb   = (const int*)d_in[2];
    const int2*   bnb   = (const int2*)d_in[3];
    const float*  wss   = (const float*)d_in[5];
    const int*    oss   = (const int*)d_in[6];
    const int2*   bns   = (const int2*)d_in[7];

    int Mb = in_sizes[3] / (D1B * 2);   // blur_neighbors_bilateral: [6, Mb, 2]
    int Ms = in_sizes[7] / (D1S * 2);   // blur_neighbors_spatial:   [3, Ms, 2]

    const int nblk = (NPIX + TPB - 1) / TPB;
    const int cblk = (Mb + Ms + TPB - 1) / TPB;
    const int bblk = (Mb + TPB - 1) / TPB;

    // ---- Init: stencils + zero, then fused ones+Q0 splat ----
    compose_zero<<<cblk, TPB>>>(bnb, Mb, bns, Ms);
    splat0<<<nblk, TPB>>>(unary, osb, wsb, oss, wss);

    // ---- Round 0: blur ones alongside Q, compute norms inline in slice ----
    k1t<1><<<cblk, TPB>>>(Mb, Ms);
    k2t<1><<<cblk, TPB>>>(Mb, bns, Ms);
    k3t<1><<<bblk, TPB>>>(Mb);
    slice_t<1><<<nblk, TPB>>>(unary, osb, wsb, oss, wss, (float4*)d_out, 0);

    // ---- Rounds 1-9 ----
    for (int it = 1; it < 10; it++) {
        k1t<0><<<cblk, TPB>>>(Mb, Ms);
        k2t<0><<<cblk, TPB>>>(Mb, bns, Ms);
        k3t<0><<<bblk, TPB>>>(Mb);
        slice_t<0><<<nblk, TPB>>>(unary, osb, wsb, oss, wss,
                                  (float4*)d_out, it == 9 ? 1 : 0);
    }
}